// round 15
// baseline (speedup 1.0000x reference)
#include <cuda_runtime.h>
#include <cuda_fp16.h>
#include <math.h>
#include <stdint.h>

// ---------------- problem constants ----------------
#define BATCH     8
#define DMODEL    192
#define DINNER    384
#define DSTATE    16
#define HIMG      128
#define WIMG      128
#define LIMG      16384
#define MROWS     131072
#define NPROJ     768

// ---------------- scratch (static device memory) ---------------------------
__device__ __half g_Winh [DMODEL * NPROJ];
__device__ __half g_Wouth[DINNER * DMODEL];
__device__ __half g_Wxh  [DINNER * 32];
__device__ __half g_Wxl  [DINNER * 32];
__device__ __half g_XIh  [(size_t)MROWS * DINNER];
__device__ __half g_ZSh  [(size_t)MROWS * DINNER];
__device__ __half g_XCh  [(size_t)MROWS * DINNER];
__device__ __half g_Yh   [(size_t)MROWS * DINNER];
__device__ float  g_XSSM [(size_t)MROWS * 32];

// ---------------- helpers --------------------------------------------------
__device__ __forceinline__ float silu_f(float v) {
    return v * __fdividef(1.f, 1.f + expf(-v));
}
__device__ __forceinline__ float softplus_f(float v) {
    return (v > 15.f) ? v : __logf(1.f + expf(v));
}
__device__ __forceinline__ uint32_t pack_h2(float a, float b) {
    __half2 h = __floats2half2_rn(a, b);
    return *(uint32_t*)&h;
}
__device__ __forceinline__ uint2 pack_h4(float4 v) {
    uint2 r;
    r.x = pack_h2(v.x, v.y);
    r.y = pack_h2(v.z, v.w);
    return r;
}
__device__ __forceinline__ float4 unpack_h4(uint2 u) {
    float2 a = __half22float2(*(__half2*)&u.x);
    float2 b = __half22float2(*(__half2*)&u.y);
    return make_float4(a.x, a.y, b.x, b.y);
}

#define LDSM4(d, addr)                                                        \
    asm volatile("ldmatrix.sync.aligned.m8n8.x4.shared.b16 {%0,%1,%2,%3},[%4];" \
        : "=r"((d).x), "=r"((d).y), "=r"((d).z), "=r"((d).w) : "r"(addr))

#define LDSM2T(d, addr)                                                       \
    asm volatile("ldmatrix.sync.aligned.m8n8.x2.trans.shared.b16 {%0,%1},[%2];" \
        : "=r"((d).x), "=r"((d).y) : "r"(addr))

#define MMA16816(d, a, b)                                                     \
    asm volatile(                                                             \
        "mma.sync.aligned.m16n8k16.row.col.f32.f16.f16.f32 "                  \
        "{%0,%1,%2,%3},{%4,%5,%6,%7},{%8,%9},{%0,%1,%2,%3};"                  \
        : "+f"((d)[0]), "+f"((d)[1]), "+f"((d)[2]), "+f"((d)[3])              \
        : "r"((a).x), "r"((a).y), "r"((a).z), "r"((a).w),                     \
          "r"((b).x), "r"((b).y))

// =====================================================================
// Kernel 0: fp32 -> fp16 conversion of WEIGHTS only
// =====================================================================
#define CV_WIN4  (DMODEL * NPROJ / 4)
#define CV_WOUT4 (DINNER * DMODEL / 4)
#define CV_WX4   (DINNER * 32 / 4)
#define CV_TOTAL4 (CV_WIN4 + CV_WOUT4 + CV_WX4)

__global__ void __launch_bounds__(256) convert_kernel(
    const float* __restrict__ w_in,
    const float* __restrict__ w_out,
    const float* __restrict__ w_x)
{
    for (int i = blockIdx.x * 256 + threadIdx.x;
         i < CV_TOTAL4; i += gridDim.x * 256) {
        if (i < CV_WIN4) {
            *(uint2*)(g_Winh + (size_t)i * 4) = pack_h4(((const float4*)w_in)[i]);
        } else if (i < CV_WIN4 + CV_WOUT4) {
            const int j = i - CV_WIN4;
            *(uint2*)(g_Wouth + (size_t)j * 4) = pack_h4(((const float4*)w_out)[j]);
        } else {
            const int j = i - CV_WIN4 - CV_WOUT4;
            float4 v = ((const float4*)w_x)[j];
            __half h0 = __float2half_rn(v.x), h1 = __float2half_rn(v.y);
            __half h2 = __float2half_rn(v.z), h3 = __float2half_rn(v.w);
            g_Wxh[j * 4 + 0] = h0; g_Wxh[j * 4 + 1] = h1;
            g_Wxh[j * 4 + 2] = h2; g_Wxh[j * 4 + 3] = h3;
            g_Wxl[j * 4 + 0] = __float2half_rn(v.x - __half2float(h0));
            g_Wxl[j * 4 + 1] = __float2half_rn(v.y - __half2float(h1));
            g_Wxl[j * 4 + 2] = __float2half_rn(v.z - __half2float(h2));
            g_Wxl[j * 4 + 3] = __float2half_rn(v.w - __half2float(h3));
        }
    }
}

// =====================================================================
// Kernel 1 (fp16 tensor): x_proj = x @ w_in ; -> XIh, ZSh(silu)
// BM=64, BN=256, BK=32, 2 CTAs/SM, in-flight fp32->fp16 A convert.
// =====================================================================
#define G1_TILES 6
#define G1_ABUF  2048
#define G1_BBUF  8192
#define G1_HBUF  (G1_ABUF + G1_BBUF)

__global__ void __launch_bounds__(256, 2) gemm_proj_f16(
    const float* __restrict__ X)
{
    extern __shared__ __half hsh[];
    const uint32_t smem_b = (uint32_t)__cvta_generic_to_shared(hsh);

    const int tid  = threadIdx.x;
    const int bn   = blockIdx.x * 256;
    const int bm   = blockIdx.y * 64;
    const int warp = tid >> 5;
    const int lane = tid & 31;
    const int wm   = warp >> 2;
    const int wn   = warp & 3;

    float acc[2][8][4];
#pragma unroll
    for (int i = 0; i < 2; ++i)
#pragma unroll
        for (int j = 0; j < 8; ++j)
#pragma unroll
            for (int c = 0; c < 4; ++c) acc[i][j][c] = 0.f;

    float4 raf[2];
    uint4  rbv[4];

#define G1_LDG(T)                                                             \
    {                                                                         \
        const int kt = (T) * 32;                                              \
        {                                                                     \
            const int row = tid >> 2, seg = tid & 3;                          \
            const float* p = X + (size_t)(bm + row) * DMODEL + kt + seg * 8;  \
            raf[0] = *(const float4*)p;                                       \
            raf[1] = *(const float4*)(p + 4);                                 \
        }                                                                     \
        _Pragma("unroll")                                                     \
        for (int i = 0; i < 4; ++i) {                                         \
            const int u = tid + 256 * i;                                      \
            const int k = u >> 5, c = u & 31;                                 \
            rbv[i] = *(const uint4*)(g_Winh + (size_t)(kt + k) * NPROJ + bn + c * 8); \
        }                                                                     \
    }

#define G1_STS(BUF)                                                           \
    {                                                                         \
        __half* sa = hsh + (BUF) * G1_HBUF;                                   \
        __half* sb = sa + G1_ABUF;                                            \
        {                                                                     \
            const int row = tid >> 2, seg = tid & 3;                          \
            uint4 pk;                                                         \
            pk.x = pack_h2(raf[0].x, raf[0].y);                               \
            pk.y = pack_h2(raf[0].z, raf[0].w);                               \
            pk.z = pack_h2(raf[1].x, raf[1].y);                               \
            pk.w = pack_h2(raf[1].z, raf[1].w);                               \
            *(uint4*)(sa + row * 32 + ((seg ^ ((row >> 1) & 3)) << 3)) = pk;  \
        }                                                                     \
        _Pragma("unroll")                                                     \
        for (int i = 0; i < 4; ++i) {                                         \
            const int u = tid + 256 * i;                                      \
            const int k = u >> 5, c = u & 31;                                 \
            *(uint4*)(sb + k * 256 + ((c ^ (k & 7)) << 3)) = rbv[i];          \
        }                                                                     \
    }

    G1_LDG(0)
    G1_STS(0)
    __syncthreads();

    for (int t = 0; t < G1_TILES; ++t) {
        const int cur = t & 1;
        if (t + 1 < G1_TILES) G1_LDG(t + 1)

        const uint32_t a_off = smem_b + cur * G1_HBUF * 2;
        const uint32_t b_off = a_off + G1_ABUF * 2;
#pragma unroll
        for (int ks = 0; ks < 2; ++ks) {
            uint4 af[2];
            uint2 bf[8];
#pragma unroll
            for (int mt = 0; mt < 2; ++mt) {
                const int row = wm * 32 + mt * 16 + (lane & 15);
                const int ch  = ks * 2 + (lane >> 4);
                LDSM4(af[mt], a_off +
                      (row * 32 + ((ch ^ ((row >> 1) & 3)) << 3)) * 2);
            }
#pragma unroll
            for (int nt = 0; nt < 8; ++nt) {
                const int k = ks * 16 + (lane & 15);
                const int c = wn * 8 + nt;
                LDSM2T(bf[nt], b_off +
                       (k * 256 + ((c ^ (k & 7)) << 3)) * 2);
            }
#pragma unroll
            for (int mt = 0; mt < 2; ++mt)
#pragma unroll
                for (int nt = 0; nt < 8; ++nt)
                    MMA16816(acc[mt][nt], af[mt], bf[nt]);
        }

        if (t + 1 < G1_TILES) {
            G1_STS(1 - cur)
            __syncthreads();
        }
    }

    const int g  = lane >> 2;
    const int tq = lane & 3;
#pragma unroll
    for (int mt = 0; mt < 2; ++mt) {
        const size_t m0 = (size_t)bm + wm * 32 + mt * 16 + g;
#pragma unroll
        for (int nt = 0; nt < 8; ++nt) {
            const int n = bn + wn * 64 + nt * 8 + 2 * tq;
            if (n < DINNER) {
                *(uint32_t*)(g_XIh + m0 * DINNER + n) =
                    pack_h2(acc[mt][nt][0], acc[mt][nt][1]);
                *(uint32_t*)(g_XIh + (m0 + 8) * DINNER + n) =
                    pack_h2(acc[mt][nt][2], acc[mt][nt][3]);
            } else {
                *(uint32_t*)(g_ZSh + m0 * DINNER + (n - DINNER)) =
                    pack_h2(silu_f(acc[mt][nt][0]), silu_f(acc[mt][nt][1]));
                *(uint32_t*)(g_ZSh + (m0 + 8) * DINNER + (n - DINNER)) =
                    pack_h2(silu_f(acc[mt][nt][2]), silu_f(acc[mt][nt][3]));
            }
        }
    }
#undef G1_LDG
#undef G1_STS
}

// =====================================================================
// Kernel 2: tiled depthwise conv 3x3 + silu : XIh -> XCh
// =====================================================================
__global__ void __launch_bounds__(256) conv_kernel(
    const float* __restrict__ w_conv, const float* __restrict__ b_conv)
{
    extern __shared__ char csh_raw[];
    __half* in_sh = (__half*)csh_raw;
    float*  wt_sh = (float*)(csh_raw + 324 * 64 * 2);
    float*  bb_sh = wt_sh + 9 * 64;

    const int cg = blockIdx.x;
    const int tx = blockIdx.y;
    const int bz = blockIdx.z;
    const int b  = bz >> 3;
    const int ty = bz & 7;
    const int h0 = ty * 16;
    const int w0 = tx * 16;
    const int tid = threadIdx.x;

    for (int i = tid; i < 9 * 64; i += 256) {
        int tap = i >> 6, c = i & 63;
        wt_sh[i] = w_conv[(cg * 64 + c) * 9 + tap];
    }
    if (tid < 64) bb_sh[tid] = b_conv[cg * 64 + tid];

    for (int i = tid; i < 324 * 8; i += 256) {
        const int pos = i >> 3;
        const int c8  = i & 7;
        const int y = pos / 18;
        const int x = pos - y * 18;
        const int gh = h0 + y - 1;
        const int gw = w0 + x - 1;
        uint4 v = make_uint4(0u, 0u, 0u, 0u);
        if (gh >= 0 && gh < HIMG && gw >= 0 && gw < WIMG) {
            const size_t row = ((size_t)b << 14) + (gh << 7) + gw;
            v = *(const uint4*)(g_XIh + row * DINNER + cg * 64 + c8 * 8);
        }
        *(uint4*)(in_sh + (size_t)pos * 64 + c8 * 8) = v;
    }
    __syncthreads();

    const int x  = tid >> 4;
    const int c4 = tid & 15;
    float4 wr[9];
#pragma unroll
    for (int t = 0; t < 9; ++t)
        wr[t] = *(float4*)(wt_sh + t * 64 + c4 * 4);
    const float4 bias = *(float4*)(bb_sh + c4 * 4);

#define CONV_LD(Y, DX)                                                        \
    unpack_h4(*(uint2*)(in_sh + (size_t)((Y) * 18 + x + (DX)) * 64 + c4 * 4))

    float4 w0r[3], w1r[3], w2r[3];
#pragma unroll
    for (int dx = 0; dx < 3; ++dx) {
        w0r[dx] = CONV_LD(0, dx);
        w1r[dx] = CONV_LD(1, dx);
    }

#pragma unroll
    for (int y = 0; y < 16; ++y) {
#pragma unroll
        for (int dx = 0; dx < 3; ++dx)
            w2r[dx] = CONV_LD(y + 2, dx);

        float4 acc = bias;
#pragma unroll
        for (int dx = 0; dx < 3; ++dx) {
            const float4 t0 = wr[dx], t1 = wr[3 + dx], t2 = wr[6 + dx];
            acc.x = fmaf(w0r[dx].x, t0.x, acc.x);
            acc.y = fmaf(w0r[dx].y, t0.y, acc.y);
            acc.z = fmaf(w0r[dx].z, t0.z, acc.z);
            acc.w = fmaf(w0r[dx].w, t0.w, acc.w);
            acc.x = fmaf(w1r[dx].x, t1.x, acc.x);
            acc.y = fmaf(w1r[dx].y, t1.y, acc.y);
            acc.z = fmaf(w1r[dx].z, t1.z, acc.z);
            acc.w = fmaf(w1r[dx].w, t1.w, acc.w);
            acc.x = fmaf(w2r[dx].x, t2.x, acc.x);
            acc.y = fmaf(w2r[dx].y, t2.y, acc.y);
            acc.z = fmaf(w2r[dx].z, t2.z, acc.z);
            acc.w = fmaf(w2r[dx].w, t2.w, acc.w);
        }
        acc.x = silu_f(acc.x);
        acc.y = silu_f(acc.y);
        acc.z = silu_f(acc.z);
        acc.w = silu_f(acc.w);
        const size_t row = ((size_t)b << 14) + ((h0 + y) << 7) + (w0 + x);
        *(uint2*)(g_XCh + row * DINNER + cg * 64 + c4 * 4) = pack_h4(acc);

#pragma unroll
        for (int dx = 0; dx < 3; ++dx) {
            w0r[dx] = w1r[dx];
            w1r[dx] = w2r[dx];
        }
    }
#undef CONV_LD
}

// =====================================================================
// Kernel 3 (fp16 tensor): XSSM = XC @ (w_x_hi + w_x_lo)
// BK=32 double-buffered A (2x8KB) + combined w_x [384][72] (hi 0..31,
// lo 40..71; stride 144B = 9x16B -> 16B-aligned, conflict-free ldmatrix).
// 70 KB smem -> 3 CTAs/SM.
// =====================================================================
#define XS_WSTRIDE 72
#define XS_ABUF (128 * 32)     // halves per A buffer

__global__ void __launch_bounds__(256) xssm_mma_kernel(void)
{
    extern __shared__ __half xhsh[];
    __half* sw = xhsh;                         // [384][72]
    __half* sa = sw + DINNER * XS_WSTRIDE;     // A double buffer
    const uint32_t sa_base = (uint32_t)__cvta_generic_to_shared(sa);
    const uint32_t sw_base = (uint32_t)__cvta_generic_to_shared(sw);

    const int tid  = threadIdx.x;
    const int warp = tid >> 5;
    const int lane = tid & 31;
    const size_t bm = (size_t)blockIdx.x * 128;

    // load w_x hi/lo into combined padded smem
    for (int i = tid; i < DINNER * 4; i += 256) {
        const int k = i >> 2;
        const int c = i & 3;
        *(uint4*)(sw + k * XS_WSTRIDE + c * 8) =
            *(const uint4*)(g_Wxh + k * 32 + c * 8);
        *(uint4*)(sw + k * XS_WSTRIDE + 40 + c * 8) =
            *(const uint4*)(g_Wxl + k * 32 + c * 8);
    }

    float acc[4][4];
#pragma unroll
    for (int nt = 0; nt < 4; ++nt)
#pragma unroll
        for (int c = 0; c < 4; ++c) acc[nt][c] = 0.f;

    uint4 rav[2];

#define XS_LDG(T)                                                             \
    {                                                                         \
        const int kt = (T) * 32;                                              \
        _Pragma("unroll")                                                     \
        for (int i = 0; i < 2; ++i) {                                         \
            const int u = tid + 256 * i;                                      \
            const int row = u >> 2, c8 = u & 3;                               \
            rav[i] = *(const uint4*)(g_XCh + (bm + row) * DINNER + kt + c8 * 8); \
        }                                                                     \
    }

#define XS_STS(BUF)                                                           \
    {                                                                         \
        __half* dst = sa + (BUF) * XS_ABUF;                                   \
        _Pragma("unroll")                                                     \
        for (int i = 0; i < 2; ++i) {                                         \
            const int u = tid + 256 * i;                                      \
            const int row = u >> 2, c8 = u & 3;                               \
            *(uint4*)(dst + row * 32 + ((c8 ^ ((row >> 1) & 3)) << 3)) = rav[i]; \
        }                                                                     \
    }

    XS_LDG(0)
    XS_STS(0)
    __syncthreads();

    for (int t = 0; t < 12; ++t) {
        const int cur = t & 1;
        if (t + 1 < 12) XS_LDG(t + 1)

        const uint32_t a_off = sa_base + cur * XS_ABUF * 2;
#pragma unroll
        for (int ks = 0; ks < 2; ++ks) {
            uint4 af;
            {
                const int row = warp * 16 + (lane & 15);
                const int ch  = ks * 2 + (lane >> 4);
                LDSM4(af, a_off +
                      (row * 32 + ((ch ^ ((row >> 1) & 3)) << 3)) * 2);
            }
            const int kg = t * 32 + ks * 16 + (lane & 15);
            uint2 bh[4], bl[4];
#pragma unroll
            for (int nt = 0; nt < 4; ++nt) {
                LDSM2T(bh[nt], sw_base + (kg * XS_WSTRIDE + nt * 8) * 2);
                LDSM2T(bl[nt], sw_base + (kg * XS_WSTRIDE + 40 + nt * 8) * 2);
            }
#pragma unroll
            for (int nt = 0; nt < 4; ++nt) {
                MMA16816(acc[nt], af, bh[nt]);
                MMA16816(acc[nt], af, bl[nt]);
            }
        }

        if (t + 1 < 12) {
            XS_STS(1 - cur)
            __syncthreads();
        }
    }

    const int g  = lane >> 2;
    const int tq = lane & 3;
    const size_t m0 = bm + warp * 16 + g;
#pragma unroll
    for (int nt = 0; nt < 4; ++nt) {
        const int n = nt * 8 + 2 * tq;
        *(float2*)(g_XSSM + m0 * 32 + n)       = make_float2(acc[nt][0], acc[nt][1]);
        *(float2*)(g_XSSM + (m0 + 8) * 32 + n) = make_float2(acc[nt][2], acc[nt][3]);
    }
#undef XS_LDG
#undef XS_STS
}

// =====================================================================
// Kernel 4: pointwise bc + dt + gate + LayerNorm -> Yh (8 rows/warp)
// =====================================================================
__global__ void __launch_bounds__(256) point_kernel(
    const float* __restrict__ w_dt,
    const float* __restrict__ b_dt,
    const float* __restrict__ D_skip,
    const float* __restrict__ gamma,
    const float* __restrict__ beta)
{
    __shared__ float4 wdt4[16 * 96];
    __shared__ float4 bdt4[96], dsk4[96], gam4[96], bet4[96];

    const int tid = threadIdx.x;
    for (int i = tid; i < 16 * 96; i += 256)
        wdt4[i] = ((const float4*)w_dt)[i];
    if (tid < 96) {
        bdt4[tid] = ((const float4*)b_dt)[tid];
        dsk4[tid] = ((const float4*)D_skip)[tid];
        gam4[tid] = ((const float4*)gamma)[tid];
        bet4[tid] = ((const float4*)beta)[tid];
    }
    __syncthreads();

    const int warp = tid >> 5;
    const int lane = tid & 31;
    const size_t wbase = ((size_t)blockIdx.x * 8 + warp) * 8;

#pragma unroll 1
    for (int it = 0; it < 4; ++it) {
        const size_t ra = wbase + it * 2;
        const size_t rb = ra + 1;

        const float va = g_XSSM[ra * 32 + lane];
        const float vb = g_XSSM[rb * 32 + lane];

        float pa = va * __shfl_xor_sync(0xffffffffu, va, 16);
        float pb = vb * __shfl_xor_sync(0xffffffffu, vb, 16);
#pragma unroll
        for (int o = 8; o; o >>= 1) {
            pa += __shfl_xor_sync(0xffffffffu, pa, o);
            pb += __shfl_xor_sync(0xffffffffu, pb, o);
        }
        const float bca = pa, bcb = pb;

        float Ba[DSTATE], Bb[DSTATE];
#pragma unroll
        for (int s = 0; s < DSTATE; ++s) {
            Ba[s] = __shfl_sync(0xffffffffu, va, s);
            Bb[s] = __shfl_sync(0xffffffffu, vb, s);
        }

        float4 ya[3], yb[3];
        float sa = 0.f, sqa = 0.f, sb = 0.f, sqb = 0.f;
#pragma unroll
        for (int k = 0; k < 3; ++k) {
            const int cf = lane + 32 * k;
            float4 dva = bdt4[cf];
            float4 dvb = dva;
#pragma unroll
            for (int s = 0; s < DSTATE; ++s) {
                const float4 w = wdt4[s * 96 + cf];
                dva.x = fmaf(Ba[s], w.x, dva.x);
                dva.y = fmaf(Ba[s], w.y, dva.y);
                dva.z = fmaf(Ba[s], w.z, dva.z);
                dva.w = fmaf(Ba[s], w.w, dva.w);
                dvb.x = fmaf(Bb[s], w.x, dvb.x);
                dvb.y = fmaf(Bb[s], w.y, dvb.y);
                dvb.z = fmaf(Bb[s], w.z, dvb.z);
                dvb.w = fmaf(Bb[s], w.w, dvb.w);
            }
            const float4 dsk = dsk4[cf];
            const float4 xca = unpack_h4(*(const uint2*)(g_XCh + ra * DINNER + cf * 4));
            const float4 xcb = unpack_h4(*(const uint2*)(g_XCh + rb * DINNER + cf * 4));
            const float4 zsa = unpack_h4(*(const uint2*)(g_ZSh + ra * DINNER + cf * 4));
            const float4 zsb = unpack_h4(*(const uint2*)(g_ZSh + rb * DINNER + cf * 4));

            float4 v;
            v.x = (softplus_f(dva.x) * bca + xca.x * dsk.x) * zsa.x;
            v.y = (softplus_f(dva.y) * bca + xca.y * dsk.y) * zsa.y;
            v.z = (softplus_f(dva.z) * bca + xca.z * dsk.z) * zsa.z;
            v.w = (softplus_f(dva.w) * bca + xca.w * dsk.w) * zsa.w;
            ya[k] = v;
            sa  += v.x + v.y + v.z + v.w;
            sqa += v.x * v.x + v.y * v.y + v.z * v.z + v.w * v.w;

            v.x = (softplus_f(dvb.x) * bcb + xcb.x * dsk.x) * zsb.x;
            v.y = (softplus_f(dvb.y) * bcb + xcb.y * dsk.y) * zsb.y;
            v.z = (softplus_f(dvb.z) * bcb + xcb.z * dsk.z) * zsb.z;
            v.w = (softplus_f(dvb.w) * bcb + xcb.w * dsk.w) * zsb.w;
            yb[k] = v;
            sb  += v.x + v.y + v.z + v.w;
            sqb += v.x * v.x + v.y * v.y + v.z * v.z + v.w * v.w;
        }

#pragma unroll
        for (int o = 16; o; o >>= 1) {
            sa  += __shfl_xor_sync(0xffffffffu, sa, o);
            sqa += __shfl_xor_sync(0xffffffffu, sqa, o);
            sb  += __shfl_xor_sync(0xffffffffu, sb, o);
            sqb += __shfl_xor_sync(0xffffffffu, sqb, o);
        }
        const float mua = sa * (1.f / 384.f);
        const float rsa = rsqrtf(sqa * (1.f / 384.f) - mua * mua + 1e-5f);
        const float mub = sb * (1.f / 384.f);
        const float rsb = rsqrtf(sqb * (1.f / 384.f) - mub * mub + 1e-5f);

#pragma unroll
        for (int k = 0; k < 3; ++k) {
            const int cf = lane + 32 * k;
            const float4 g = gam4[cf];
            const float4 be = bet4[cf];
            float4 o;
            o.x = (ya[k].x - mua) * rsa * g.x + be.x;
            o.y = (ya[k].y - mua) * rsa * g.y + be.y;
            o.z = (ya[k].z - mua) * rsa * g.z + be.z;
            o.w = (ya[k].w - mua) * rsa * g.w + be.w;
            *(uint2*)(g_Yh + ra * DINNER + cf * 4) = pack_h4(o);
            o.x = (yb[k].x - mub) * rsb * g.x + be.x;
            o.y = (yb[k].y - mub) * rsb * g.y + be.y;
            o.z = (yb[k].z - mub) * rsb * g.z + be.z;
            o.w = (yb[k].w - mub) * rsb * g.w + be.w;
            *(uint2*)(g_Yh + rb * DINNER + cf * 4) = pack_h4(o);
        }
    }
}

// =====================================================================
// Kernel 5 (fp16 tensor): out = Y @ w_out, transposed write [B,192,L]
// BM=64, BN=192, 2 CTAs/SM. Direct scatter stores (32B-sector aligned).
// =====================================================================
#define G3_TILES 12
#define G3_ABUF  2048
#define G3_BBUF  6144
#define G3_HBUF  (G3_ABUF + G3_BBUF)

__global__ void __launch_bounds__(256, 2) gemm_out_f16(float* __restrict__ OUT)
{
    extern __shared__ __half hsh[];
    const uint32_t smem_b = (uint32_t)__cvta_generic_to_shared(hsh);

    const int tid  = threadIdx.x;
    const size_t bm = (size_t)blockIdx.x * 64;
    const int warp = tid >> 5;
    const int lane = tid & 31;
    const int wm   = warp >> 2;
    const int wn   = warp & 3;

    float acc[2][6][4];
#pragma unroll
    for (int i = 0; i < 2; ++i)
#pragma unroll
        for (int j = 0; j < 6; ++j)
#pragma unroll
            for (int c = 0; c < 4; ++c) acc[i][j][c] = 0.f;

    uint4 rav, rbv[3];

#define G3_LDG(T)                                                             \
    {                                                                         \
        const int kt = (T) * 32;                                              \
        {                                                                     \
            const int row = tid >> 2, seg = tid & 3;                          \
            rav = *(const uint4*)(g_Yh + (bm + row) * DINNER + kt + seg * 8); \
        }                                                                     \
        _Pragma("unroll")                                                     \
        for (int i = 0; i < 3; ++i) {                                         \
            const int u = tid + 256 * i;                                      \
            const int k = u / 24, c = u - k * 24;                             \
            rbv[i] = *(const uint4*)(g_Wouth + (size_t)(kt + k) * DMODEL + c * 8); \
        }                                                                     \
    }

#define G3_STS(BUF)                                                           \
    {                                                                         \
        __half* sa = hsh + (BUF) * G3_HBUF;                                   \
        __half* sb = sa + G3_ABUF;                                            \
        {                                                                     \
            const int row = tid >> 2, seg = tid & 3;                          \
            *(uint4*)(sa + row * 32 + ((seg ^ ((row >> 1) & 3)) << 3)) = rav; \
        }                                                                     \
        _Pragma("unroll")                                                     \
        for (int i = 0; i < 3; ++i) {                                         \
            const int u = tid + 256 * i;                                      \
            const int k = u / 24, c = u - k * 24;                             \
            *(uint4*)(sb + k * 192 + ((c ^ (k & 7)) << 3)) = rbv[i];          \
        }                                                                     \
    }

    G3_LDG(0)
    G3_STS(0)
    __syncthreads();

    for (int t = 0; t < G3_TILES; ++t) {
        const int cur = t & 1;
        if (t + 1 < G3_TILES) G3_LDG(t + 1)

        const uint32_t a_off = smem_b + cur * G3_HBUF * 2;
        const uint32_t b_off = a_off + G3_ABUF * 2;
#pragma unroll
        for (int ks = 0; ks < 2; ++ks) {
            uint4 af[2];
            uint2 bf[6];
#pragma unroll
            for (int mt = 0; mt < 2; ++mt) {
                const int row = wm * 32 + mt * 16 + (lane & 15);
                const int ch  = ks * 2 + (lane >> 4);
                LDSM4(af[mt], a_off +
                      (row * 32 + ((ch ^ ((row >> 1) & 3)) << 3)) * 2);
            }
#pragma unroll
            for (int nt = 0; nt < 6; ++nt) {
                const int k = ks * 16 + (lane & 15);
                const int c = wn * 6 + nt;
                LDSM2T(bf[nt], b_off +
                       (k * 192 + ((c ^ (k & 7)) << 3)) * 2);
            }
#pragma unroll
            for (int mt = 0; mt < 2; ++mt)
#pragma unroll
                for (int nt = 0; nt < 6; ++nt)
                    MMA16816(acc[mt][nt], af[mt], bf[nt]);
        }

        if (t + 1 < G3_TILES) {
            G3_STS(1 - cur)
            __syncthreads();
        }
    }

    const int g  = lane >> 2;
    const int tq = lane & 3;
#pragma unroll
    for (int mt = 0; mt < 2; ++mt) {
        const size_t m0 = bm + wm * 32 + mt * 16 + g;
        const int b0 = (int)(m0 >> 14);
        const int l0 = (int)(m0 & 16383);
        const int b1 = (int)((m0 + 8) >> 14);
        const int l1 = (int)((m0 + 8) & 16383);
#pragma unroll
        for (int nt = 0; nt < 6; ++nt) {
            const int n = wn * 48 + nt * 8 + 2 * tq;
            OUT[((size_t)b0 * DMODEL + n)     * LIMG + l0] = acc[mt][nt][0];
            OUT[((size_t)b0 * DMODEL + n + 1) * LIMG + l0] = acc[mt][nt][1];
            OUT[((size_t)b1 * DMODEL + n)     * LIMG + l1] = acc[mt][nt][2];
            OUT[((size_t)b1 * DMODEL + n + 1) * LIMG + l1] = acc[mt][nt][3];
        }
    }
#undef G3_LDG
#undef G3_STS
}

// =====================================================================
extern "C" void kernel_launch(void* const* d_in, const int* in_sizes, int n_in,
                              void* d_out, int out_size) {
    (void)in_sizes; (void)n_in; (void)out_size;
    const float* x      = (const float*)d_in[0];
    const float* w_in   = (const float*)d_in[1];
    const float* w_conv = (const float*)d_in[2];
    const float* b_conv = (const float*)d_in[3];
    const float* w_x    = (const float*)d_in[4];
    const float* w_dt   = (const float*)d_in[5];
    const float* b_dt   = (const float*)d_in[6];
    const float* D_skip = (const float*)d_in[7];
    const float* w_out  = (const float*)d_in[8];
    const float* gamma  = (const float*)d_in[9];
    const float* beta   = (const float*)d_in[10];
    float* out = (float*)d_out;

    const int g1_smem   = 2 * G1_HBUF * 2;                          // 40 KB
    const int g3_smem   = 2 * G3_HBUF * 2;                          // 32 KB
    const int conv_smem = 324 * 64 * 2 + (9 * 64 + 64) * 4;         // ~44 KB
    const int xs_smem   = (DINNER * XS_WSTRIDE + 2 * XS_ABUF) * 2;  // 70 KB
    cudaFuncSetAttribute(gemm_proj_f16,
        cudaFuncAttributeMaxDynamicSharedMemorySize, g1_smem);
    cudaFuncSetAttribute(gemm_out_f16,
        cudaFuncAttributeMaxDynamicSharedMemorySize, g3_smem);
    cudaFuncSetAttribute(conv_kernel,
        cudaFuncAttributeMaxDynamicSharedMemorySize, conv_smem);
    cudaFuncSetAttribute(xssm_mma_kernel,
        cudaFuncAttributeMaxDynamicSharedMemorySize, xs_smem);

    // 0. fp32 -> fp16 weight conversions
    convert_kernel<<<256, 256>>>(w_in, w_out, w_x);

    // 1. projection GEMM (in-flight fp16 convert of x)
    dim3 g1(NPROJ / 256, MROWS / 64);
    gemm_proj_f16<<<g1, 256, g1_smem>>>(x);

    // 2. depthwise conv + silu
    dim3 g2(6, 8, 64);
    conv_kernel<<<g2, 256, conv_smem>>>(w_conv, b_conv);

    // 3. XSSM via fp16 MMA (3 CTAs/SM)
    xssm_mma_kernel<<<MROWS / 128, 256, xs_smem>>>();

    // 4. pointwise dt/gate/LN (8 rows/warp)
    point_kernel<<<MROWS / 64, 256>>>(w_dt, b_dt, D_skip, gamma, beta);

    // 5. output GEMM (transposed scatter write)
    gemm_out_f16<<<MROWS / 64, 256, g3_smem>>>(out);
}

// round 16
// speedup vs baseline: 1.0577x; 1.0577x over previous
#include <cuda_runtime.h>
#include <cuda_fp16.h>
#include <math.h>
#include <stdint.h>

// ---------------- problem constants ----------------
#define BATCH     8
#define DMODEL    192
#define DINNER    384
#define DSTATE    16
#define HIMG      128
#define WIMG      128
#define LIMG      16384
#define MROWS     131072
#define NPROJ     768

// ---------------- scratch (static device memory) ---------------------------
__device__ __half g_Winh [DMODEL * NPROJ];
__device__ __half g_Wouth[DINNER * DMODEL];
__device__ __half g_Wxh  [DINNER * 32];
__device__ __half g_Wxl  [DINNER * 32];
__device__ __half g_XIh  [(size_t)MROWS * DINNER];
__device__ __half g_ZSh  [(size_t)MROWS * DINNER];
__device__ __half g_XCh  [(size_t)MROWS * DINNER];
__device__ __half g_Yh   [(size_t)MROWS * DINNER];
__device__ float  g_XSSM [(size_t)MROWS * 32];

// ---------------- helpers --------------------------------------------------
__device__ __forceinline__ float silu_f(float v) {
    return v * __fdividef(1.f, 1.f + expf(-v));
}
__device__ __forceinline__ float softplus_f(float v) {
    return (v > 15.f) ? v : __logf(1.f + expf(v));
}
__device__ __forceinline__ uint32_t pack_h2(float a, float b) {
    __half2 h = __floats2half2_rn(a, b);
    return *(uint32_t*)&h;
}
__device__ __forceinline__ uint2 pack_h4(float4 v) {
    uint2 r;
    r.x = pack_h2(v.x, v.y);
    r.y = pack_h2(v.z, v.w);
    return r;
}
__device__ __forceinline__ float4 unpack_h4(uint2 u) {
    float2 a = __half22float2(*(__half2*)&u.x);
    float2 b = __half22float2(*(__half2*)&u.y);
    return make_float4(a.x, a.y, b.x, b.y);
}

#define LDSM4(d, addr)                                                        \
    asm volatile("ldmatrix.sync.aligned.m8n8.x4.shared.b16 {%0,%1,%2,%3},[%4];" \
        : "=r"((d).x), "=r"((d).y), "=r"((d).z), "=r"((d).w) : "r"(addr))

#define LDSM2T(d, addr)                                                       \
    asm volatile("ldmatrix.sync.aligned.m8n8.x2.trans.shared.b16 {%0,%1},[%2];" \
        : "=r"((d).x), "=r"((d).y) : "r"(addr))

#define MMA16816(d, a, b)                                                     \
    asm volatile(                                                             \
        "mma.sync.aligned.m16n8k16.row.col.f32.f16.f16.f32 "                  \
        "{%0,%1,%2,%3},{%4,%5,%6,%7},{%8,%9},{%0,%1,%2,%3};"                  \
        : "+f"((d)[0]), "+f"((d)[1]), "+f"((d)[2]), "+f"((d)[3])              \
        : "r"((a).x), "r"((a).y), "r"((a).z), "r"((a).w),                     \
          "r"((b).x), "r"((b).y))

#define CP16(dst_u32, src_ptr)                                                \
    asm volatile("cp.async.cg.shared.global [%0], [%1], 16;"                  \
        :: "r"(dst_u32), "l"(src_ptr))
#define CP_COMMIT() asm volatile("cp.async.commit_group;" ::: "memory")
#define CP_WAIT0()  asm volatile("cp.async.wait_group 0;" ::: "memory")

// =====================================================================
// Kernel 0: fp32 -> fp16 conversion of WEIGHTS only
// =====================================================================
#define CV_WIN4  (DMODEL * NPROJ / 4)
#define CV_WOUT4 (DINNER * DMODEL / 4)
#define CV_WX4   (DINNER * 32 / 4)
#define CV_TOTAL4 (CV_WIN4 + CV_WOUT4 + CV_WX4)

__global__ void __launch_bounds__(256) convert_kernel(
    const float* __restrict__ w_in,
    const float* __restrict__ w_out,
    const float* __restrict__ w_x)
{
    for (int i = blockIdx.x * 256 + threadIdx.x;
         i < CV_TOTAL4; i += gridDim.x * 256) {
        if (i < CV_WIN4) {
            *(uint2*)(g_Winh + (size_t)i * 4) = pack_h4(((const float4*)w_in)[i]);
        } else if (i < CV_WIN4 + CV_WOUT4) {
            const int j = i - CV_WIN4;
            *(uint2*)(g_Wouth + (size_t)j * 4) = pack_h4(((const float4*)w_out)[j]);
        } else {
            const int j = i - CV_WIN4 - CV_WOUT4;
            float4 v = ((const float4*)w_x)[j];
            __half h0 = __float2half_rn(v.x), h1 = __float2half_rn(v.y);
            __half h2 = __float2half_rn(v.z), h3 = __float2half_rn(v.w);
            g_Wxh[j * 4 + 0] = h0; g_Wxh[j * 4 + 1] = h1;
            g_Wxh[j * 4 + 2] = h2; g_Wxh[j * 4 + 3] = h3;
            g_Wxl[j * 4 + 0] = __float2half_rn(v.x - __half2float(h0));
            g_Wxl[j * 4 + 1] = __float2half_rn(v.y - __half2float(h1));
            g_Wxl[j * 4 + 2] = __float2half_rn(v.z - __half2float(h2));
            g_Wxl[j * 4 + 3] = __float2half_rn(v.w - __half2float(h3));
        }
    }
}

// =====================================================================
// Kernel 1 (fp16 tensor): x_proj = x @ w_in ; -> XIh, ZSh(silu)
// BM=64, BN=256, BK=32, 2 CTAs/SM.
// A: LDG fp32 + in-register convert + STS. B: cp.async.
// =====================================================================
#define G1_TILES 6
#define G1_ABUF  2048
#define G1_BBUF  8192
#define G1_HBUF  (G1_ABUF + G1_BBUF)

__global__ void __launch_bounds__(256, 2) gemm_proj_f16(
    const float* __restrict__ X)
{
    extern __shared__ __half hsh[];
    const uint32_t smem_b = (uint32_t)__cvta_generic_to_shared(hsh);

    const int tid  = threadIdx.x;
    const int bn   = blockIdx.x * 256;
    const int bm   = blockIdx.y * 64;
    const int warp = tid >> 5;
    const int lane = tid & 31;
    const int wm   = warp >> 2;
    const int wn   = warp & 3;

    float acc[2][8][4];
#pragma unroll
    for (int i = 0; i < 2; ++i)
#pragma unroll
        for (int j = 0; j < 8; ++j)
#pragma unroll
            for (int c = 0; c < 4; ++c) acc[i][j][c] = 0.f;

    float4 raf[2];
    const int a_row = tid >> 2, a_seg = tid & 3;

#define G1_LDGA(T)                                                            \
    {                                                                         \
        const float* p = X + (size_t)(bm + a_row) * DMODEL + (T) * 32 + a_seg * 8; \
        raf[0] = *(const float4*)p;                                           \
        raf[1] = *(const float4*)(p + 4);                                     \
    }

#define G1_STSA(BUF)                                                          \
    {                                                                         \
        __half* sa = hsh + (BUF) * G1_HBUF;                                   \
        uint4 pk;                                                             \
        pk.x = pack_h2(raf[0].x, raf[0].y);                                   \
        pk.y = pack_h2(raf[0].z, raf[0].w);                                   \
        pk.z = pack_h2(raf[1].x, raf[1].y);                                   \
        pk.w = pack_h2(raf[1].z, raf[1].w);                                   \
        *(uint4*)(sa + a_row * 32 + ((a_seg ^ ((a_row >> 1) & 3)) << 3)) = pk; \
    }

#define G1_CPB(T, BUF)                                                        \
    {                                                                         \
        const int kt = (T) * 32;                                              \
        const uint32_t sb = smem_b + ((BUF) * G1_HBUF + G1_ABUF) * 2;         \
        _Pragma("unroll")                                                     \
        for (int i = 0; i < 4; ++i) {                                         \
            const int u = tid + 256 * i;                                      \
            const int k = u >> 5, c = u & 31;                                 \
            CP16(sb + (k * 256 + ((c ^ (k & 7)) << 3)) * 2,                   \
                 g_Winh + (size_t)(kt + k) * NPROJ + bn + c * 8);             \
        }                                                                     \
    }

    G1_LDGA(0)
    G1_CPB(0, 0)
    CP_COMMIT();
    G1_STSA(0)
    CP_WAIT0();
    __syncthreads();

    for (int t = 0; t < G1_TILES; ++t) {
        const int cur = t & 1;
        if (t + 1 < G1_TILES) {
            G1_LDGA(t + 1)
            G1_CPB(t + 1, 1 - cur)
            CP_COMMIT();
        }

        const uint32_t a_off = smem_b + cur * G1_HBUF * 2;
        const uint32_t b_off = a_off + G1_ABUF * 2;
#pragma unroll
        for (int ks = 0; ks < 2; ++ks) {
            uint4 af[2];
            uint2 bf[8];
#pragma unroll
            for (int mt = 0; mt < 2; ++mt) {
                const int row = wm * 32 + mt * 16 + (lane & 15);
                const int ch  = ks * 2 + (lane >> 4);
                LDSM4(af[mt], a_off +
                      (row * 32 + ((ch ^ ((row >> 1) & 3)) << 3)) * 2);
            }
#pragma unroll
            for (int nt = 0; nt < 8; ++nt) {
                const int k = ks * 16 + (lane & 15);
                const int c = wn * 8 + nt;
                LDSM2T(bf[nt], b_off +
                       (k * 256 + ((c ^ (k & 7)) << 3)) * 2);
            }
#pragma unroll
            for (int mt = 0; mt < 2; ++mt)
#pragma unroll
                for (int nt = 0; nt < 8; ++nt)
                    MMA16816(acc[mt][nt], af[mt], bf[nt]);
        }

        if (t + 1 < G1_TILES) {
            G1_STSA(1 - cur)
            CP_WAIT0();
            __syncthreads();
        }
    }

    const int g  = lane >> 2;
    const int tq = lane & 3;
#pragma unroll
    for (int mt = 0; mt < 2; ++mt) {
        const size_t m0 = (size_t)bm + wm * 32 + mt * 16 + g;
#pragma unroll
        for (int nt = 0; nt < 8; ++nt) {
            const int n = bn + wn * 64 + nt * 8 + 2 * tq;
            if (n < DINNER) {
                *(uint32_t*)(g_XIh + m0 * DINNER + n) =
                    pack_h2(acc[mt][nt][0], acc[mt][nt][1]);
                *(uint32_t*)(g_XIh + (m0 + 8) * DINNER + n) =
                    pack_h2(acc[mt][nt][2], acc[mt][nt][3]);
            } else {
                *(uint32_t*)(g_ZSh + m0 * DINNER + (n - DINNER)) =
                    pack_h2(silu_f(acc[mt][nt][0]), silu_f(acc[mt][nt][1]));
                *(uint32_t*)(g_ZSh + (m0 + 8) * DINNER + (n - DINNER)) =
                    pack_h2(silu_f(acc[mt][nt][2]), silu_f(acc[mt][nt][3]));
            }
        }
    }
#undef G1_LDGA
#undef G1_STSA
#undef G1_CPB
}

// =====================================================================
// Kernel 2: tiled depthwise conv 3x3 + silu : XIh -> XCh  [unchanged]
// =====================================================================
__global__ void __launch_bounds__(256) conv_kernel(
    const float* __restrict__ w_conv, const float* __restrict__ b_conv)
{
    extern __shared__ char csh_raw[];
    __half* in_sh = (__half*)csh_raw;
    float*  wt_sh = (float*)(csh_raw + 324 * 64 * 2);
    float*  bb_sh = wt_sh + 9 * 64;

    const int cg = blockIdx.x;
    const int tx = blockIdx.y;
    const int bz = blockIdx.z;
    const int b  = bz >> 3;
    const int ty = bz & 7;
    const int h0 = ty * 16;
    const int w0 = tx * 16;
    const int tid = threadIdx.x;

    for (int i = tid; i < 9 * 64; i += 256) {
        int tap = i >> 6, c = i & 63;
        wt_sh[i] = w_conv[(cg * 64 + c) * 9 + tap];
    }
    if (tid < 64) bb_sh[tid] = b_conv[cg * 64 + tid];

    for (int i = tid; i < 324 * 8; i += 256) {
        const int pos = i >> 3;
        const int c8  = i & 7;
        const int y = pos / 18;
        const int x = pos - y * 18;
        const int gh = h0 + y - 1;
        const int gw = w0 + x - 1;
        uint4 v = make_uint4(0u, 0u, 0u, 0u);
        if (gh >= 0 && gh < HIMG && gw >= 0 && gw < WIMG) {
            const size_t row = ((size_t)b << 14) + (gh << 7) + gw;
            v = *(const uint4*)(g_XIh + row * DINNER + cg * 64 + c8 * 8);
        }
        *(uint4*)(in_sh + (size_t)pos * 64 + c8 * 8) = v;
    }
    __syncthreads();

    const int x  = tid >> 4;
    const int c4 = tid & 15;
    float4 wr[9];
#pragma unroll
    for (int t = 0; t < 9; ++t)
        wr[t] = *(float4*)(wt_sh + t * 64 + c4 * 4);
    const float4 bias = *(float4*)(bb_sh + c4 * 4);

#define CONV_LD(Y, DX)                                                        \
    unpack_h4(*(uint2*)(in_sh + (size_t)((Y) * 18 + x + (DX)) * 64 + c4 * 4))

    float4 w0r[3], w1r[3], w2r[3];
#pragma unroll
    for (int dx = 0; dx < 3; ++dx) {
        w0r[dx] = CONV_LD(0, dx);
        w1r[dx] = CONV_LD(1, dx);
    }

#pragma unroll
    for (int y = 0; y < 16; ++y) {
#pragma unroll
        for (int dx = 0; dx < 3; ++dx)
            w2r[dx] = CONV_LD(y + 2, dx);

        float4 acc = bias;
#pragma unroll
        for (int dx = 0; dx < 3; ++dx) {
            const float4 t0 = wr[dx], t1 = wr[3 + dx], t2 = wr[6 + dx];
            acc.x = fmaf(w0r[dx].x, t0.x, acc.x);
            acc.y = fmaf(w0r[dx].y, t0.y, acc.y);
            acc.z = fmaf(w0r[dx].z, t0.z, acc.z);
            acc.w = fmaf(w0r[dx].w, t0.w, acc.w);
            acc.x = fmaf(w1r[dx].x, t1.x, acc.x);
            acc.y = fmaf(w1r[dx].y, t1.y, acc.y);
            acc.z = fmaf(w1r[dx].z, t1.z, acc.z);
            acc.w = fmaf(w1r[dx].w, t1.w, acc.w);
            acc.x = fmaf(w2r[dx].x, t2.x, acc.x);
            acc.y = fmaf(w2r[dx].y, t2.y, acc.y);
            acc.z = fmaf(w2r[dx].z, t2.z, acc.z);
            acc.w = fmaf(w2r[dx].w, t2.w, acc.w);
        }
        acc.x = silu_f(acc.x);
        acc.y = silu_f(acc.y);
        acc.z = silu_f(acc.z);
        acc.w = silu_f(acc.w);
        const size_t row = ((size_t)b << 14) + ((h0 + y) << 7) + (w0 + x);
        *(uint2*)(g_XCh + row * DINNER + cg * 64 + c4 * 4) = pack_h4(acc);

#pragma unroll
        for (int dx = 0; dx < 3; ++dx) {
            w0r[dx] = w1r[dx];
            w1r[dx] = w2r[dx];
        }
    }
#undef CONV_LD
}

// =====================================================================
// Kernel 3 (fp16 tensor): XSSM = XC @ (w_x_hi + w_x_lo)
// R14 layout (BK=64, separate hi/lo), tiles loaded via cp.async.
// =====================================================================
#define XS_BSTRIDE 40
#define XS_ABUF (128 * 64)

__global__ void __launch_bounds__(256) xssm_mma_kernel(void)
{
    extern __shared__ __half xhsh[];
    __half* sbh = xhsh;
    __half* sbl = sbh + DINNER * XS_BSTRIDE;
    __half* sa  = sbl + DINNER * XS_BSTRIDE;
    const uint32_t sa_base  = (uint32_t)__cvta_generic_to_shared(sa);
    const uint32_t sbh_base = (uint32_t)__cvta_generic_to_shared(sbh);
    const uint32_t sbl_base = (uint32_t)__cvta_generic_to_shared(sbl);

    const int tid  = threadIdx.x;
    const int warp = tid >> 5;
    const int lane = tid & 31;
    const size_t bm = (size_t)blockIdx.x * 128;

    // weights via cp.async
    for (int i = tid; i < DINNER * 4; i += 256) {
        const int k = i >> 2;
        const int c = i & 3;
        CP16(sbh_base + (k * XS_BSTRIDE + c * 8) * 2, g_Wxh + k * 32 + c * 8);
        CP16(sbl_base + (k * XS_BSTRIDE + c * 8) * 2, g_Wxl + k * 32 + c * 8);
    }

    float acc[4][4];
#pragma unroll
    for (int nt = 0; nt < 4; ++nt)
#pragma unroll
        for (int c = 0; c < 4; ++c) acc[nt][c] = 0.f;

#define XS_CP(T, BUF)                                                         \
    {                                                                         \
        const int kt = (T) * 64;                                              \
        const uint32_t dst = sa_base + (BUF) * XS_ABUF * 2;                   \
        _Pragma("unroll")                                                     \
        for (int i = 0; i < 4; ++i) {                                         \
            const int u = tid + 256 * i;                                      \
            const int row = u >> 3, c8 = u & 7;                               \
            CP16(dst + (row * 64 + ((c8 ^ (row & 7)) << 3)) * 2,              \
                 g_XCh + (bm + row) * DINNER + kt + c8 * 8);                  \
        }                                                                     \
    }

    XS_CP(0, 0)
    CP_COMMIT();
    CP_WAIT0();
    __syncthreads();

    for (int t = 0; t < 6; ++t) {
        const int cur = t & 1;
        if (t + 1 < 6) {
            XS_CP(t + 1, 1 - cur)
            CP_COMMIT();
        }

        const uint32_t a_off = sa_base + cur * XS_ABUF * 2;
#pragma unroll
        for (int ks = 0; ks < 4; ++ks) {
            uint4 af;
            {
                const int row = warp * 16 + (lane & 15);
                const int ch  = ks * 2 + (lane >> 4);
                LDSM4(af, a_off + (row * 64 + ((ch ^ (row & 7)) << 3)) * 2);
            }
            const int kg = t * 64 + ks * 16 + (lane & 15);
            uint2 bh[4], bl[4];
#pragma unroll
            for (int nt = 0; nt < 4; ++nt) {
                LDSM2T(bh[nt], sbh_base + (kg * XS_BSTRIDE + nt * 8) * 2);
                LDSM2T(bl[nt], sbl_base + (kg * XS_BSTRIDE + nt * 8) * 2);
            }
#pragma unroll
            for (int nt = 0; nt < 4; ++nt) {
                MMA16816(acc[nt], af, bh[nt]);
                MMA16816(acc[nt], af, bl[nt]);
            }
        }

        if (t + 1 < 6) {
            CP_WAIT0();
            __syncthreads();
        }
    }

    const int g  = lane >> 2;
    const int tq = lane & 3;
    const size_t m0 = bm + warp * 16 + g;
#pragma unroll
    for (int nt = 0; nt < 4; ++nt) {
        const int n = nt * 8 + 2 * tq;
        *(float2*)(g_XSSM + m0 * 32 + n)       = make_float2(acc[nt][0], acc[nt][1]);
        *(float2*)(g_XSSM + (m0 + 8) * 32 + n) = make_float2(acc[nt][2], acc[nt][3]);
    }
#undef XS_CP
}

// =====================================================================
// Kernel 4: pointwise bc + dt + gate + LayerNorm -> Yh (8 rows/warp)
// =====================================================================
__global__ void __launch_bounds__(256) point_kernel(
    const float* __restrict__ w_dt,
    const float* __restrict__ b_dt,
    const float* __restrict__ D_skip,
    const float* __restrict__ gamma,
    const float* __restrict__ beta)
{
    __shared__ float4 wdt4[16 * 96];
    __shared__ float4 bdt4[96], dsk4[96], gam4[96], bet4[96];

    const int tid = threadIdx.x;
    for (int i = tid; i < 16 * 96; i += 256)
        wdt4[i] = ((const float4*)w_dt)[i];
    if (tid < 96) {
        bdt4[tid] = ((const float4*)b_dt)[tid];
        dsk4[tid] = ((const float4*)D_skip)[tid];
        gam4[tid] = ((const float4*)gamma)[tid];
        bet4[tid] = ((const float4*)beta)[tid];
    }
    __syncthreads();

    const int warp = tid >> 5;
    const int lane = tid & 31;
    const size_t wbase = ((size_t)blockIdx.x * 8 + warp) * 8;

#pragma unroll 1
    for (int it = 0; it < 4; ++it) {
        const size_t ra = wbase + it * 2;
        const size_t rb = ra + 1;

        const float va = g_XSSM[ra * 32 + lane];
        const float vb = g_XSSM[rb * 32 + lane];

        float pa = va * __shfl_xor_sync(0xffffffffu, va, 16);
        float pb = vb * __shfl_xor_sync(0xffffffffu, vb, 16);
#pragma unroll
        for (int o = 8; o; o >>= 1) {
            pa += __shfl_xor_sync(0xffffffffu, pa, o);
            pb += __shfl_xor_sync(0xffffffffu, pb, o);
        }
        const float bca = pa, bcb = pb;

        float Ba[DSTATE], Bb[DSTATE];
#pragma unroll
        for (int s = 0; s < DSTATE; ++s) {
            Ba[s] = __shfl_sync(0xffffffffu, va, s);
            Bb[s] = __shfl_sync(0xffffffffu, vb, s);
        }

        float4 ya[3], yb[3];
        float sa = 0.f, sqa = 0.f, sb = 0.f, sqb = 0.f;
#pragma unroll
        for (int k = 0; k < 3; ++k) {
            const int cf = lane + 32 * k;
            float4 dva = bdt4[cf];
            float4 dvb = dva;
#pragma unroll
            for (int s = 0; s < DSTATE; ++s) {
                const float4 w = wdt4[s * 96 + cf];
                dva.x = fmaf(Ba[s], w.x, dva.x);
                dva.y = fmaf(Ba[s], w.y, dva.y);
                dva.z = fmaf(Ba[s], w.z, dva.z);
                dva.w = fmaf(Ba[s], w.w, dva.w);
                dvb.x = fmaf(Bb[s], w.x, dvb.x);
                dvb.y = fmaf(Bb[s], w.y, dvb.y);
                dvb.z = fmaf(Bb[s], w.z, dvb.z);
                dvb.w = fmaf(Bb[s], w.w, dvb.w);
            }
            const float4 dsk = dsk4[cf];
            const float4 xca = unpack_h4(*(const uint2*)(g_XCh + ra * DINNER + cf * 4));
            const float4 xcb = unpack_h4(*(const uint2*)(g_XCh + rb * DINNER + cf * 4));
            const float4 zsa = unpack_h4(*(const uint2*)(g_ZSh + ra * DINNER + cf * 4));
            const float4 zsb = unpack_h4(*(const uint2*)(g_ZSh + rb * DINNER + cf * 4));

            float4 v;
            v.x = (softplus_f(dva.x) * bca + xca.x * dsk.x) * zsa.x;
            v.y = (softplus_f(dva.y) * bca + xca.y * dsk.y) * zsa.y;
            v.z = (softplus_f(dva.z) * bca + xca.z * dsk.z) * zsa.z;
            v.w = (softplus_f(dva.w) * bca + xca.w * dsk.w) * zsa.w;
            ya[k] = v;
            sa  += v.x + v.y + v.z + v.w;
            sqa += v.x * v.x + v.y * v.y + v.z * v.z + v.w * v.w;

            v.x = (softplus_f(dvb.x) * bcb + xcb.x * dsk.x) * zsb.x;
            v.y = (softplus_f(dvb.y) * bcb + xcb.y * dsk.y) * zsb.y;
            v.z = (softplus_f(dvb.z) * bcb + xcb.z * dsk.z) * zsb.z;
            v.w = (softplus_f(dvb.w) * bcb + xcb.w * dsk.w) * zsb.w;
            yb[k] = v;
            sb  += v.x + v.y + v.z + v.w;
            sqb += v.x * v.x + v.y * v.y + v.z * v.z + v.w * v.w;
        }

#pragma unroll
        for (int o = 16; o; o >>= 1) {
            sa  += __shfl_xor_sync(0xffffffffu, sa, o);
            sqa += __shfl_xor_sync(0xffffffffu, sqa, o);
            sb  += __shfl_xor_sync(0xffffffffu, sb, o);
            sqb += __shfl_xor_sync(0xffffffffu, sqb, o);
        }
        const float mua = sa * (1.f / 384.f);
        const float rsa = rsqrtf(sqa * (1.f / 384.f) - mua * mua + 1e-5f);
        const float mub = sb * (1.f / 384.f);
        const float rsb = rsqrtf(sqb * (1.f / 384.f) - mub * mub + 1e-5f);

#pragma unroll
        for (int k = 0; k < 3; ++k) {
            const int cf = lane + 32 * k;
            const float4 g = gam4[cf];
            const float4 be = bet4[cf];
            float4 o;
            o.x = (ya[k].x - mua) * rsa * g.x + be.x;
            o.y = (ya[k].y - mua) * rsa * g.y + be.y;
            o.z = (ya[k].z - mua) * rsa * g.z + be.z;
            o.w = (ya[k].w - mua) * rsa * g.w + be.w;
            *(uint2*)(g_Yh + ra * DINNER + cf * 4) = pack_h4(o);
            o.x = (yb[k].x - mub) * rsb * g.x + be.x;
            o.y = (yb[k].y - mub) * rsb * g.y + be.y;
            o.z = (yb[k].z - mub) * rsb * g.z + be.z;
            o.w = (yb[k].w - mub) * rsb * g.w + be.w;
            *(uint2*)(g_Yh + rb * DINNER + cf * 4) = pack_h4(o);
        }
    }
}

// =====================================================================
// Kernel 5 (fp16 tensor): out = Y @ w_out, transposed write [B,192,L]
// BM=64, BN=192, 2 CTAs/SM. A and B tiles via cp.async.
// =====================================================================
#define G3_TILES 12
#define G3_ABUF  2048
#define G3_BBUF  6144
#define G3_HBUF  (G3_ABUF + G3_BBUF)

__global__ void __launch_bounds__(256, 2) gemm_out_f16(float* __restrict__ OUT)
{
    extern __shared__ __half hsh[];
    const uint32_t smem_b = (uint32_t)__cvta_generic_to_shared(hsh);

    const int tid  = threadIdx.x;
    const size_t bm = (size_t)blockIdx.x * 64;
    const int warp = tid >> 5;
    const int lane = tid & 31;
    const int wm   = warp >> 2;
    const int wn   = warp & 3;

    float acc[2][6][4];
#pragma unroll
    for (int i = 0; i < 2; ++i)
#pragma unroll
        for (int j = 0; j < 6; ++j)
#pragma unroll
            for (int c = 0; c < 4; ++c) acc[i][j][c] = 0.f;

#define G3_CP(T, BUF)                                                         \
    {                                                                         \
        const int kt = (T) * 32;                                              \
        const uint32_t sa = smem_b + (BUF) * G3_HBUF * 2;                     \
        const uint32_t sb = sa + G3_ABUF * 2;                                 \
        {                                                                     \
            const int row = tid >> 2, seg = tid & 3;                          \
            CP16(sa + (row * 32 + ((seg ^ ((row >> 1) & 3)) << 3)) * 2,       \
                 g_Yh + (bm + row) * DINNER + kt + seg * 8);                  \
        }                                                                     \
        _Pragma("unroll")                                                     \
        for (int i = 0; i < 3; ++i) {                                         \
            const int u = tid + 256 * i;                                      \
            const int k = u / 24, c = u - k * 24;                             \
            CP16(sb + (k * 192 + ((c ^ (k & 7)) << 3)) * 2,                   \
                 g_Wouth + (size_t)(kt + k) * DMODEL + c * 8);                \
        }                                                                     \
    }

    G3_CP(0, 0)
    CP_COMMIT();
    CP_WAIT0();
    __syncthreads();

    for (int t = 0; t < G3_TILES; ++t) {
        const int cur = t & 1;
        if (t + 1 < G3_TILES) {
            G3_CP(t + 1, 1 - cur)
            CP_COMMIT();
        }

        const uint32_t a_off = smem_b + cur * G3_HBUF * 2;
        const uint32_t b_off = a_off + G3_ABUF * 2;
#pragma unroll
        for (int ks = 0; ks < 2; ++ks) {
            uint4 af[2];
            uint2 bf[6];
#pragma unroll
            for (int mt = 0; mt < 2; ++mt) {
                const int row = wm * 32 + mt * 16 + (lane & 15);
                const int ch  = ks * 2 + (lane >> 4);
                LDSM4(af[mt], a_off +
                      (row * 32 + ((ch ^ ((row >> 1) & 3)) << 3)) * 2);
            }
#pragma unroll
            for (int nt = 0; nt < 6; ++nt) {
                const int k = ks * 16 + (lane & 15);
                const int c = wn * 6 + nt;
                LDSM2T(bf[nt], b_off +
                       (k * 192 + ((c ^ (k & 7)) << 3)) * 2);
            }
#pragma unroll
            for (int mt = 0; mt < 2; ++mt)
#pragma unroll
                for (int nt = 0; nt < 6; ++nt)
                    MMA16816(acc[mt][nt], af[mt], bf[nt]);
        }

        if (t + 1 < G3_TILES) {
            CP_WAIT0();
            __syncthreads();
        }
    }

    const int g  = lane >> 2;
    const int tq = lane & 3;
#pragma unroll
    for (int mt = 0; mt < 2; ++mt) {
        const size_t m0 = bm + wm * 32 + mt * 16 + g;
        const int b0 = (int)(m0 >> 14);
        const int l0 = (int)(m0 & 16383);
        const int b1 = (int)((m0 + 8) >> 14);
        const int l1 = (int)((m0 + 8) & 16383);
#pragma unroll
        for (int nt = 0; nt < 6; ++nt) {
            const int n = wn * 48 + nt * 8 + 2 * tq;
            OUT[((size_t)b0 * DMODEL + n)     * LIMG + l0] = acc[mt][nt][0];
            OUT[((size_t)b0 * DMODEL + n + 1) * LIMG + l0] = acc[mt][nt][1];
            OUT[((size_t)b1 * DMODEL + n)     * LIMG + l1] = acc[mt][nt][2];
            OUT[((size_t)b1 * DMODEL + n + 1) * LIMG + l1] = acc[mt][nt][3];
        }
    }
#undef G3_CP
}

// =====================================================================
extern "C" void kernel_launch(void* const* d_in, const int* in_sizes, int n_in,
                              void* d_out, int out_size) {
    (void)in_sizes; (void)n_in; (void)out_size;
    const float* x      = (const float*)d_in[0];
    const float* w_in   = (const float*)d_in[1];
    const float* w_conv = (const float*)d_in[2];
    const float* b_conv = (const float*)d_in[3];
    const float* w_x    = (const float*)d_in[4];
    const float* w_dt   = (const float*)d_in[5];
    const float* b_dt   = (const float*)d_in[6];
    const float* D_skip = (const float*)d_in[7];
    const float* w_out  = (const float*)d_in[8];
    const float* gamma  = (const float*)d_in[9];
    const float* beta   = (const float*)d_in[10];
    float* out = (float*)d_out;

    const int g1_smem   = 2 * G1_HBUF * 2;                          // 40 KB
    const int g3_smem   = 2 * G3_HBUF * 2;                          // 32 KB
    const int conv_smem = 324 * 64 * 2 + (9 * 64 + 64) * 4;         // ~44 KB
    const int xs_smem   = (2 * DINNER * XS_BSTRIDE + 2 * XS_ABUF) * 2; // ~94 KB
    cudaFuncSetAttribute(gemm_proj_f16,
        cudaFuncAttributeMaxDynamicSharedMemorySize, g1_smem);
    cudaFuncSetAttribute(gemm_out_f16,
        cudaFuncAttributeMaxDynamicSharedMemorySize, g3_smem);
    cudaFuncSetAttribute(conv_kernel,
        cudaFuncAttributeMaxDynamicSharedMemorySize, conv_smem);
    cudaFuncSetAttribute(xssm_mma_kernel,
        cudaFuncAttributeMaxDynamicSharedMemorySize, xs_smem);

    // 0. fp32 -> fp16 weight conversions
    convert_kernel<<<256, 256>>>(w_in, w_out, w_x);

    // 1. projection GEMM (cp.async B, in-register A convert)
    dim3 g1(NPROJ / 256, MROWS / 64);
    gemm_proj_f16<<<g1, 256, g1_smem>>>(x);

    // 2. depthwise conv + silu
    dim3 g2(6, 8, 64);
    conv_kernel<<<g2, 256, conv_smem>>>(w_conv, b_conv);

    // 3. XSSM via fp16 MMA (cp.async tiles)
    xssm_mma_kernel<<<MROWS / 128, 256, xs_smem>>>();

    // 4. pointwise dt/gate/LN
    point_kernel<<<MROWS / 64, 256>>>(w_dt, b_dt, D_skip, gamma, beta);

    // 5. output GEMM (cp.async tiles, transposed scatter write)
    gemm_out_f16<<<MROWS / 64, 256, g3_smem>>>(out);
}

// round 17
// speedup vs baseline: 1.0820x; 1.0230x over previous
#include <cuda_runtime.h>
#include <cuda_fp16.h>
#include <math.h>
#include <stdint.h>

// ---------------- problem constants ----------------
#define BATCH     8
#define DMODEL    192
#define DINNER    384
#define DSTATE    16
#define HIMG      128
#define WIMG      128
#define LIMG      16384
#define MROWS     131072
#define NPROJ     768

// ---------------- scratch (static device memory) ---------------------------
__device__ __half g_Winh [DMODEL * NPROJ];
__device__ __half g_Wouth[DINNER * DMODEL];
__device__ __half g_Wxh  [DINNER * 32];
__device__ __half g_Wxl  [DINNER * 32];
__device__ __half g_XIh  [(size_t)MROWS * DINNER];
__device__ __half g_ZSh  [(size_t)MROWS * DINNER];
__device__ __half g_XCh  [(size_t)MROWS * DINNER];
__device__ __half g_Yh   [(size_t)MROWS * DINNER];
__device__ float  g_XSSM [(size_t)MROWS * 32];

// ---------------- helpers --------------------------------------------------
__device__ __forceinline__ float silu_f(float v) {
    return v * __fdividef(1.f, 1.f + expf(-v));
}
__device__ __forceinline__ float softplus_f(float v) {
    return (v > 15.f) ? v : __logf(1.f + expf(v));
}
__device__ __forceinline__ uint32_t pack_h2(float a, float b) {
    __half2 h = __floats2half2_rn(a, b);
    return *(uint32_t*)&h;
}
__device__ __forceinline__ uint2 pack_h4(float4 v) {
    uint2 r;
    r.x = pack_h2(v.x, v.y);
    r.y = pack_h2(v.z, v.w);
    return r;
}
__device__ __forceinline__ float4 unpack_h4(uint2 u) {
    float2 a = __half22float2(*(__half2*)&u.x);
    float2 b = __half22float2(*(__half2*)&u.y);
    return make_float4(a.x, a.y, b.x, b.y);
}

#define LDSM4(d, addr)                                                        \
    asm volatile("ldmatrix.sync.aligned.m8n8.x4.shared.b16 {%0,%1,%2,%3},[%4];" \
        : "=r"((d).x), "=r"((d).y), "=r"((d).z), "=r"((d).w) : "r"(addr))

#define LDSM2T(d, addr)                                                       \
    asm volatile("ldmatrix.sync.aligned.m8n8.x2.trans.shared.b16 {%0,%1},[%2];" \
        : "=r"((d).x), "=r"((d).y) : "r"(addr))

#define MMA16816(d, a, b)                                                     \
    asm volatile(                                                             \
        "mma.sync.aligned.m16n8k16.row.col.f32.f16.f16.f32 "                  \
        "{%0,%1,%2,%3},{%4,%5,%6,%7},{%8,%9},{%0,%1,%2,%3};"                  \
        : "+f"((d)[0]), "+f"((d)[1]), "+f"((d)[2]), "+f"((d)[3])              \
        : "r"((a).x), "r"((a).y), "r"((a).z), "r"((a).w),                     \
          "r"((b).x), "r"((b).y))

#define CP16(dst_u32, src_ptr)                                                \
    asm volatile("cp.async.cg.shared.global [%0], [%1], 16;"                  \
        :: "r"(dst_u32), "l"(src_ptr))
#define CP_COMMIT() asm volatile("cp.async.commit_group;" ::: "memory")
#define CP_WAIT0()  asm volatile("cp.async.wait_group 0;" ::: "memory")
#define CP_WAIT1()  asm volatile("cp.async.wait_group 1;" ::: "memory")

// =====================================================================
// Kernel 0: fp32 -> fp16 conversion of WEIGHTS only
// =====================================================================
#define CV_WIN4  (DMODEL * NPROJ / 4)
#define CV_WOUT4 (DINNER * DMODEL / 4)
#define CV_WX4   (DINNER * 32 / 4)
#define CV_TOTAL4 (CV_WIN4 + CV_WOUT4 + CV_WX4)

__global__ void __launch_bounds__(256) convert_kernel(
    const float* __restrict__ w_in,
    const float* __restrict__ w_out,
    const float* __restrict__ w_x)
{
    for (int i = blockIdx.x * 256 + threadIdx.x;
         i < CV_TOTAL4; i += gridDim.x * 256) {
        if (i < CV_WIN4) {
            *(uint2*)(g_Winh + (size_t)i * 4) = pack_h4(((const float4*)w_in)[i]);
        } else if (i < CV_WIN4 + CV_WOUT4) {
            const int j = i - CV_WIN4;
            *(uint2*)(g_Wouth + (size_t)j * 4) = pack_h4(((const float4*)w_out)[j]);
        } else {
            const int j = i - CV_WIN4 - CV_WOUT4;
            float4 v = ((const float4*)w_x)[j];
            __half h0 = __float2half_rn(v.x), h1 = __float2half_rn(v.y);
            __half h2 = __float2half_rn(v.z), h3 = __float2half_rn(v.w);
            g_Wxh[j * 4 + 0] = h0; g_Wxh[j * 4 + 1] = h1;
            g_Wxh[j * 4 + 2] = h2; g_Wxh[j * 4 + 3] = h3;
            g_Wxl[j * 4 + 0] = __float2half_rn(v.x - __half2float(h0));
            g_Wxl[j * 4 + 1] = __float2half_rn(v.y - __half2float(h1));
            g_Wxl[j * 4 + 2] = __float2half_rn(v.z - __half2float(h2));
            g_Wxl[j * 4 + 3] = __float2half_rn(v.w - __half2float(h3));
        }
    }
}

// =====================================================================
// Kernel 1 (fp16 tensor): x_proj = x @ w_in ; -> XIh, ZSh(silu)
// BM=64, BN=256, BK=32, 3-stage cp.async pipeline, 2 CTAs/SM.
// A: LDG fp32 + in-register convert + STS (into stage t+2).
// =====================================================================
#define G1_TILES 6
#define G1_ABUF  2048
#define G1_BBUF  8192
#define G1_HBUF  (G1_ABUF + G1_BBUF)

__global__ void __launch_bounds__(256, 2) gemm_proj_f16(
    const float* __restrict__ X)
{
    extern __shared__ __half hsh[];
    const uint32_t smem_b = (uint32_t)__cvta_generic_to_shared(hsh);

    const int tid  = threadIdx.x;
    const int bn   = blockIdx.x * 256;
    const int bm   = blockIdx.y * 64;
    const int warp = tid >> 5;
    const int lane = tid & 31;
    const int wm   = warp >> 2;
    const int wn   = warp & 3;

    float acc[2][8][4];
#pragma unroll
    for (int i = 0; i < 2; ++i)
#pragma unroll
        for (int j = 0; j < 8; ++j)
#pragma unroll
            for (int c = 0; c < 4; ++c) acc[i][j][c] = 0.f;

    float4 raf[2];
    const int a_row = tid >> 2, a_seg = tid & 3;

#define G1_LDGA(T)                                                            \
    {                                                                         \
        const float* p = X + (size_t)(bm + a_row) * DMODEL + (T) * 32 + a_seg * 8; \
        raf[0] = *(const float4*)p;                                           \
        raf[1] = *(const float4*)(p + 4);                                     \
    }

#define G1_STSA(BUF)                                                          \
    {                                                                         \
        __half* sa = hsh + (BUF) * G1_HBUF;                                   \
        uint4 pk;                                                             \
        pk.x = pack_h2(raf[0].x, raf[0].y);                                   \
        pk.y = pack_h2(raf[0].z, raf[0].w);                                   \
        pk.z = pack_h2(raf[1].x, raf[1].y);                                   \
        pk.w = pack_h2(raf[1].z, raf[1].w);                                   \
        *(uint4*)(sa + a_row * 32 + ((a_seg ^ ((a_row >> 1) & 3)) << 3)) = pk; \
    }

#define G1_CPB(T, BUF)                                                        \
    {                                                                         \
        const int kt = (T) * 32;                                              \
        const uint32_t sb = smem_b + ((BUF) * G1_HBUF + G1_ABUF) * 2;         \
        _Pragma("unroll")                                                     \
        for (int i = 0; i < 4; ++i) {                                         \
            const int u = tid + 256 * i;                                      \
            const int k = u >> 5, c = u & 31;                                 \
            CP16(sb + (k * 256 + ((c ^ (k & 7)) << 3)) * 2,                   \
                 g_Winh + (size_t)(kt + k) * NPROJ + bn + c * 8);             \
        }                                                                     \
    }

    // prologue: stages 0 and 1
    G1_LDGA(0)
    G1_CPB(0, 0)
    CP_COMMIT();
    G1_STSA(0)
    G1_LDGA(1)
    G1_CPB(1, 1)
    CP_COMMIT();
    G1_STSA(1)
    CP_WAIT1();
    __syncthreads();

    for (int t = 0; t < G1_TILES; ++t) {
        const int cur = t % 3;
        const int nxt2 = (t + 2) % 3;
        if (t + 2 < G1_TILES) {
            G1_LDGA(t + 2)
            G1_CPB(t + 2, nxt2)
            CP_COMMIT();
        }

        const uint32_t a_off = smem_b + cur * G1_HBUF * 2;
        const uint32_t b_off = a_off + G1_ABUF * 2;
#pragma unroll
        for (int ks = 0; ks < 2; ++ks) {
            uint4 af[2];
            uint2 bf[8];
#pragma unroll
            for (int mt = 0; mt < 2; ++mt) {
                const int row = wm * 32 + mt * 16 + (lane & 15);
                const int ch  = ks * 2 + (lane >> 4);
                LDSM4(af[mt], a_off +
                      (row * 32 + ((ch ^ ((row >> 1) & 3)) << 3)) * 2);
            }
#pragma unroll
            for (int nt = 0; nt < 8; ++nt) {
                const int k = ks * 16 + (lane & 15);
                const int c = wn * 8 + nt;
                LDSM2T(bf[nt], b_off +
                       (k * 256 + ((c ^ (k & 7)) << 3)) * 2);
            }
#pragma unroll
            for (int mt = 0; mt < 2; ++mt)
#pragma unroll
                for (int nt = 0; nt < 8; ++nt)
                    MMA16816(acc[mt][nt], af[mt], bf[nt]);
        }

        if (t + 2 < G1_TILES) G1_STSA(nxt2)
        if (t + 1 < G1_TILES) {
            if (t + 2 < G1_TILES) { CP_WAIT1(); } else { CP_WAIT0(); }
            __syncthreads();
        }
    }

    const int g  = lane >> 2;
    const int tq = lane & 3;
#pragma unroll
    for (int mt = 0; mt < 2; ++mt) {
        const size_t m0 = (size_t)bm + wm * 32 + mt * 16 + g;
#pragma unroll
        for (int nt = 0; nt < 8; ++nt) {
            const int n = bn + wn * 64 + nt * 8 + 2 * tq;
            if (n < DINNER) {
                *(uint32_t*)(g_XIh + m0 * DINNER + n) =
                    pack_h2(acc[mt][nt][0], acc[mt][nt][1]);
                *(uint32_t*)(g_XIh + (m0 + 8) * DINNER + n) =
                    pack_h2(acc[mt][nt][2], acc[mt][nt][3]);
            } else {
                *(uint32_t*)(g_ZSh + m0 * DINNER + (n - DINNER)) =
                    pack_h2(silu_f(acc[mt][nt][0]), silu_f(acc[mt][nt][1]));
                *(uint32_t*)(g_ZSh + (m0 + 8) * DINNER + (n - DINNER)) =
                    pack_h2(silu_f(acc[mt][nt][2]), silu_f(acc[mt][nt][3]));
            }
        }
    }
#undef G1_LDGA
#undef G1_STSA
#undef G1_CPB
}

// =====================================================================
// Kernel 2: tiled depthwise conv 3x3 + silu : XIh -> XCh  [unchanged]
// =====================================================================
__global__ void __launch_bounds__(256) conv_kernel(
    const float* __restrict__ w_conv, const float* __restrict__ b_conv)
{
    extern __shared__ char csh_raw[];
    __half* in_sh = (__half*)csh_raw;
    float*  wt_sh = (float*)(csh_raw + 324 * 64 * 2);
    float*  bb_sh = wt_sh + 9 * 64;

    const int cg = blockIdx.x;
    const int tx = blockIdx.y;
    const int bz = blockIdx.z;
    const int b  = bz >> 3;
    const int ty = bz & 7;
    const int h0 = ty * 16;
    const int w0 = tx * 16;
    const int tid = threadIdx.x;

    for (int i = tid; i < 9 * 64; i += 256) {
        int tap = i >> 6, c = i & 63;
        wt_sh[i] = w_conv[(cg * 64 + c) * 9 + tap];
    }
    if (tid < 64) bb_sh[tid] = b_conv[cg * 64 + tid];

    for (int i = tid; i < 324 * 8; i += 256) {
        const int pos = i >> 3;
        const int c8  = i & 7;
        const int y = pos / 18;
        const int x = pos - y * 18;
        const int gh = h0 + y - 1;
        const int gw = w0 + x - 1;
        uint4 v = make_uint4(0u, 0u, 0u, 0u);
        if (gh >= 0 && gh < HIMG && gw >= 0 && gw < WIMG) {
            const size_t row = ((size_t)b << 14) + (gh << 7) + gw;
            v = *(const uint4*)(g_XIh + row * DINNER + cg * 64 + c8 * 8);
        }
        *(uint4*)(in_sh + (size_t)pos * 64 + c8 * 8) = v;
    }
    __syncthreads();

    const int x  = tid >> 4;
    const int c4 = tid & 15;
    float4 wr[9];
#pragma unroll
    for (int t = 0; t < 9; ++t)
        wr[t] = *(float4*)(wt_sh + t * 64 + c4 * 4);
    const float4 bias = *(float4*)(bb_sh + c4 * 4);

#define CONV_LD(Y, DX)                                                        \
    unpack_h4(*(uint2*)(in_sh + (size_t)((Y) * 18 + x + (DX)) * 64 + c4 * 4))

    float4 w0r[3], w1r[3], w2r[3];
#pragma unroll
    for (int dx = 0; dx < 3; ++dx) {
        w0r[dx] = CONV_LD(0, dx);
        w1r[dx] = CONV_LD(1, dx);
    }

#pragma unroll
    for (int y = 0; y < 16; ++y) {
#pragma unroll
        for (int dx = 0; dx < 3; ++dx)
            w2r[dx] = CONV_LD(y + 2, dx);

        float4 acc = bias;
#pragma unroll
        for (int dx = 0; dx < 3; ++dx) {
            const float4 t0 = wr[dx], t1 = wr[3 + dx], t2 = wr[6 + dx];
            acc.x = fmaf(w0r[dx].x, t0.x, acc.x);
            acc.y = fmaf(w0r[dx].y, t0.y, acc.y);
            acc.z = fmaf(w0r[dx].z, t0.z, acc.z);
            acc.w = fmaf(w0r[dx].w, t0.w, acc.w);
            acc.x = fmaf(w1r[dx].x, t1.x, acc.x);
            acc.y = fmaf(w1r[dx].y, t1.y, acc.y);
            acc.z = fmaf(w1r[dx].z, t1.z, acc.z);
            acc.w = fmaf(w1r[dx].w, t1.w, acc.w);
            acc.x = fmaf(w2r[dx].x, t2.x, acc.x);
            acc.y = fmaf(w2r[dx].y, t2.y, acc.y);
            acc.z = fmaf(w2r[dx].z, t2.z, acc.z);
            acc.w = fmaf(w2r[dx].w, t2.w, acc.w);
        }
        acc.x = silu_f(acc.x);
        acc.y = silu_f(acc.y);
        acc.z = silu_f(acc.z);
        acc.w = silu_f(acc.w);
        const size_t row = ((size_t)b << 14) + ((h0 + y) << 7) + (w0 + x);
        *(uint2*)(g_XCh + row * DINNER + cg * 64 + c4 * 4) = pack_h4(acc);

#pragma unroll
        for (int dx = 0; dx < 3; ++dx) {
            w0r[dx] = w1r[dx];
            w1r[dx] = w2r[dx];
        }
    }
#undef CONV_LD
}

// =====================================================================
// Kernel 3 (fp16 tensor): XSSM = XC @ (w_x_hi + w_x_lo)
// BK=64, 2-stage cp.async (3rd stage would drop occupancy).
// =====================================================================
#define XS_BSTRIDE 40
#define XS_ABUF (128 * 64)

__global__ void __launch_bounds__(256) xssm_mma_kernel(void)
{
    extern __shared__ __half xhsh[];
    __half* sbh = xhsh;
    __half* sbl = sbh + DINNER * XS_BSTRIDE;
    __half* sa  = sbl + DINNER * XS_BSTRIDE;
    const uint32_t sa_base  = (uint32_t)__cvta_generic_to_shared(sa);
    const uint32_t sbh_base = (uint32_t)__cvta_generic_to_shared(sbh);
    const uint32_t sbl_base = (uint32_t)__cvta_generic_to_shared(sbl);

    const int tid  = threadIdx.x;
    const int warp = tid >> 5;
    const int lane = tid & 31;
    const size_t bm = (size_t)blockIdx.x * 128;

    for (int i = tid; i < DINNER * 4; i += 256) {
        const int k = i >> 2;
        const int c = i & 3;
        CP16(sbh_base + (k * XS_BSTRIDE + c * 8) * 2, g_Wxh + k * 32 + c * 8);
        CP16(sbl_base + (k * XS_BSTRIDE + c * 8) * 2, g_Wxl + k * 32 + c * 8);
    }

    float acc[4][4];
#pragma unroll
    for (int nt = 0; nt < 4; ++nt)
#pragma unroll
        for (int c = 0; c < 4; ++c) acc[nt][c] = 0.f;

#define XS_CP(T, BUF)                                                         \
    {                                                                         \
        const int kt = (T) * 64;                                              \
        const uint32_t dst = sa_base + (BUF) * XS_ABUF * 2;                   \
        _Pragma("unroll")                                                     \
        for (int i = 0; i < 4; ++i) {                                         \
            const int u = tid + 256 * i;                                      \
            const int row = u >> 3, c8 = u & 7;                               \
            CP16(dst + (row * 64 + ((c8 ^ (row & 7)) << 3)) * 2,              \
                 g_XCh + (bm + row) * DINNER + kt + c8 * 8);                  \
        }                                                                     \
    }

    XS_CP(0, 0)
    CP_COMMIT();
    CP_WAIT0();
    __syncthreads();

    for (int t = 0; t < 6; ++t) {
        const int cur = t & 1;
        if (t + 1 < 6) {
            XS_CP(t + 1, 1 - cur)
            CP_COMMIT();
        }

        const uint32_t a_off = sa_base + cur * XS_ABUF * 2;
#pragma unroll
        for (int ks = 0; ks < 4; ++ks) {
            uint4 af;
            {
                const int row = warp * 16 + (lane & 15);
                const int ch  = ks * 2 + (lane >> 4);
                LDSM4(af, a_off + (row * 64 + ((ch ^ (row & 7)) << 3)) * 2);
            }
            const int kg = t * 64 + ks * 16 + (lane & 15);
            uint2 bh[4], bl[4];
#pragma unroll
            for (int nt = 0; nt < 4; ++nt) {
                LDSM2T(bh[nt], sbh_base + (kg * XS_BSTRIDE + nt * 8) * 2);
                LDSM2T(bl[nt], sbl_base + (kg * XS_BSTRIDE + nt * 8) * 2);
            }
#pragma unroll
            for (int nt = 0; nt < 4; ++nt) {
                MMA16816(acc[nt], af, bh[nt]);
                MMA16816(acc[nt], af, bl[nt]);
            }
        }

        if (t + 1 < 6) {
            CP_WAIT0();
            __syncthreads();
        }
    }

    const int g  = lane >> 2;
    const int tq = lane & 3;
    const size_t m0 = bm + warp * 16 + g;
#pragma unroll
    for (int nt = 0; nt < 4; ++nt) {
        const int n = nt * 8 + 2 * tq;
        *(float2*)(g_XSSM + m0 * 32 + n)       = make_float2(acc[nt][0], acc[nt][1]);
        *(float2*)(g_XSSM + (m0 + 8) * 32 + n) = make_float2(acc[nt][2], acc[nt][3]);
    }
#undef XS_CP
}

// =====================================================================
// Kernel 4: pointwise bc + dt + gate + LayerNorm -> Yh (8 rows/warp)
// =====================================================================
__global__ void __launch_bounds__(256) point_kernel(
    const float* __restrict__ w_dt,
    const float* __restrict__ b_dt,
    const float* __restrict__ D_skip,
    const float* __restrict__ gamma,
    const float* __restrict__ beta)
{
    __shared__ float4 wdt4[16 * 96];
    __shared__ float4 bdt4[96], dsk4[96], gam4[96], bet4[96];

    const int tid = threadIdx.x;
    for (int i = tid; i < 16 * 96; i += 256)
        wdt4[i] = ((const float4*)w_dt)[i];
    if (tid < 96) {
        bdt4[tid] = ((const float4*)b_dt)[tid];
        dsk4[tid] = ((const float4*)D_skip)[tid];
        gam4[tid] = ((const float4*)gamma)[tid];
        bet4[tid] = ((const float4*)beta)[tid];
    }
    __syncthreads();

    const int warp = tid >> 5;
    const int lane = tid & 31;
    const size_t wbase = ((size_t)blockIdx.x * 8 + warp) * 8;

#pragma unroll 1
    for (int it = 0; it < 4; ++it) {
        const size_t ra = wbase + it * 2;
        const size_t rb = ra + 1;

        const float va = g_XSSM[ra * 32 + lane];
        const float vb = g_XSSM[rb * 32 + lane];

        float pa = va * __shfl_xor_sync(0xffffffffu, va, 16);
        float pb = vb * __shfl_xor_sync(0xffffffffu, vb, 16);
#pragma unroll
        for (int o = 8; o; o >>= 1) {
            pa += __shfl_xor_sync(0xffffffffu, pa, o);
            pb += __shfl_xor_sync(0xffffffffu, pb, o);
        }
        const float bca = pa, bcb = pb;

        float Ba[DSTATE], Bb[DSTATE];
#pragma unroll
        for (int s = 0; s < DSTATE; ++s) {
            Ba[s] = __shfl_sync(0xffffffffu, va, s);
            Bb[s] = __shfl_sync(0xffffffffu, vb, s);
        }

        float4 ya[3], yb[3];
        float sa = 0.f, sqa = 0.f, sb = 0.f, sqb = 0.f;
#pragma unroll
        for (int k = 0; k < 3; ++k) {
            const int cf = lane + 32 * k;
            float4 dva = bdt4[cf];
            float4 dvb = dva;
#pragma unroll
            for (int s = 0; s < DSTATE; ++s) {
                const float4 w = wdt4[s * 96 + cf];
                dva.x = fmaf(Ba[s], w.x, dva.x);
                dva.y = fmaf(Ba[s], w.y, dva.y);
                dva.z = fmaf(Ba[s], w.z, dva.z);
                dva.w = fmaf(Ba[s], w.w, dva.w);
                dvb.x = fmaf(Bb[s], w.x, dvb.x);
                dvb.y = fmaf(Bb[s], w.y, dvb.y);
                dvb.z = fmaf(Bb[s], w.z, dvb.z);
                dvb.w = fmaf(Bb[s], w.w, dvb.w);
            }
            const float4 dsk = dsk4[cf];
            const float4 xca = unpack_h4(*(const uint2*)(g_XCh + ra * DINNER + cf * 4));
            const float4 xcb = unpack_h4(*(const uint2*)(g_XCh + rb * DINNER + cf * 4));
            const float4 zsa = unpack_h4(*(const uint2*)(g_ZSh + ra * DINNER + cf * 4));
            const float4 zsb = unpack_h4(*(const uint2*)(g_ZSh + rb * DINNER + cf * 4));

            float4 v;
            v.x = (softplus_f(dva.x) * bca + xca.x * dsk.x) * zsa.x;
            v.y = (softplus_f(dva.y) * bca + xca.y * dsk.y) * zsa.y;
            v.z = (softplus_f(dva.z) * bca + xca.z * dsk.z) * zsa.z;
            v.w = (softplus_f(dva.w) * bca + xca.w * dsk.w) * zsa.w;
            ya[k] = v;
            sa  += v.x + v.y + v.z + v.w;
            sqa += v.x * v.x + v.y * v.y + v.z * v.z + v.w * v.w;

            v.x = (softplus_f(dvb.x) * bcb + xcb.x * dsk.x) * zsb.x;
            v.y = (softplus_f(dvb.y) * bcb + xcb.y * dsk.y) * zsb.y;
            v.z = (softplus_f(dvb.z) * bcb + xcb.z * dsk.z) * zsb.z;
            v.w = (softplus_f(dvb.w) * bcb + xcb.w * dsk.w) * zsb.w;
            yb[k] = v;
            sb  += v.x + v.y + v.z + v.w;
            sqb += v.x * v.x + v.y * v.y + v.z * v.z + v.w * v.w;
        }

#pragma unroll
        for (int o = 16; o; o >>= 1) {
            sa  += __shfl_xor_sync(0xffffffffu, sa, o);
            sqa += __shfl_xor_sync(0xffffffffu, sqa, o);
            sb  += __shfl_xor_sync(0xffffffffu, sb, o);
            sqb += __shfl_xor_sync(0xffffffffu, sqb, o);
        }
        const float mua = sa * (1.f / 384.f);
        const float rsa = rsqrtf(sqa * (1.f / 384.f) - mua * mua + 1e-5f);
        const float mub = sb * (1.f / 384.f);
        const float rsb = rsqrtf(sqb * (1.f / 384.f) - mub * mub + 1e-5f);

#pragma unroll
        for (int k = 0; k < 3; ++k) {
            const int cf = lane + 32 * k;
            const float4 g = gam4[cf];
            const float4 be = bet4[cf];
            float4 o;
            o.x = (ya[k].x - mua) * rsa * g.x + be.x;
            o.y = (ya[k].y - mua) * rsa * g.y + be.y;
            o.z = (ya[k].z - mua) * rsa * g.z + be.z;
            o.w = (ya[k].w - mua) * rsa * g.w + be.w;
            *(uint2*)(g_Yh + ra * DINNER + cf * 4) = pack_h4(o);
            o.x = (yb[k].x - mub) * rsb * g.x + be.x;
            o.y = (yb[k].y - mub) * rsb * g.y + be.y;
            o.z = (yb[k].z - mub) * rsb * g.z + be.z;
            o.w = (yb[k].w - mub) * rsb * g.w + be.w;
            *(uint2*)(g_Yh + rb * DINNER + cf * 4) = pack_h4(o);
        }
    }
}

// =====================================================================
// Kernel 5 (fp16 tensor): out = Y @ w_out, transposed write [B,192,L]
// BM=64, BN=192, 3-stage cp.async pipeline, 2 CTAs/SM.
// =====================================================================
#define G3_TILES 12
#define G3_ABUF  2048
#define G3_BBUF  6144
#define G3_HBUF  (G3_ABUF + G3_BBUF)

__global__ void __launch_bounds__(256, 2) gemm_out_f16(float* __restrict__ OUT)
{
    extern __shared__ __half hsh[];
    const uint32_t smem_b = (uint32_t)__cvta_generic_to_shared(hsh);

    const int tid  = threadIdx.x;
    const size_t bm = (size_t)blockIdx.x * 64;
    const int warp = tid >> 5;
    const int lane = tid & 31;
    const int wm   = warp >> 2;
    const int wn   = warp & 3;

    float acc[2][6][4];
#pragma unroll
    for (int i = 0; i < 2; ++i)
#pragma unroll
        for (int j = 0; j < 6; ++j)
#pragma unroll
            for (int c = 0; c < 4; ++c) acc[i][j][c] = 0.f;

#define G3_CP(T, BUF)                                                         \
    {                                                                         \
        const int kt = (T) * 32;                                              \
        const uint32_t sa = smem_b + (BUF) * G3_HBUF * 2;                     \
        const uint32_t sb = sa + G3_ABUF * 2;                                 \
        {                                                                     \
            const int row = tid >> 2, seg = tid & 3;                          \
            CP16(sa + (row * 32 + ((seg ^ ((row >> 1) & 3)) << 3)) * 2,       \
                 g_Yh + (bm + row) * DINNER + kt + seg * 8);                  \
        }                                                                     \
        _Pragma("unroll")                                                     \
        for (int i = 0; i < 3; ++i) {                                         \
            const int u = tid + 256 * i;                                      \
            const int k = u / 24, c = u - k * 24;                             \
            CP16(sb + (k * 192 + ((c ^ (k & 7)) << 3)) * 2,                   \
                 g_Wouth + (size_t)(kt + k) * DMODEL + c * 8);                \
        }                                                                     \
    }

    G3_CP(0, 0)
    CP_COMMIT();
    G3_CP(1, 1)
    CP_COMMIT();
    CP_WAIT1();
    __syncthreads();

    for (int t = 0; t < G3_TILES; ++t) {
        const int cur = t % 3;
        if (t + 2 < G3_TILES) {
            G3_CP(t + 2, (t + 2) % 3)
            CP_COMMIT();
        }

        const uint32_t a_off = smem_b + cur * G3_HBUF * 2;
        const uint32_t b_off = a_off + G3_ABUF * 2;
#pragma unroll
        for (int ks = 0; ks < 2; ++ks) {
            uint4 af[2];
            uint2 bf[6];
#pragma unroll
            for (int mt = 0; mt < 2; ++mt) {
                const int row = wm * 32 + mt * 16 + (lane & 15);
                const int ch  = ks * 2 + (lane >> 4);
                LDSM4(af[mt], a_off +
                      (row * 32 + ((ch ^ ((row >> 1) & 3)) << 3)) * 2);
            }
#pragma unroll
            for (int nt = 0; nt < 6; ++nt) {
                const int k = ks * 16 + (lane & 15);
                const int c = wn * 6 + nt;
                LDSM2T(bf[nt], b_off +
                       (k * 192 + ((c ^ (k & 7)) << 3)) * 2);
            }
#pragma unroll
            for (int mt = 0; mt < 2; ++mt)
#pragma unroll
                for (int nt = 0; nt < 6; ++nt)
                    MMA16816(acc[mt][nt], af[mt], bf[nt]);
        }

        if (t + 1 < G3_TILES) {
            if (t + 2 < G3_TILES) { CP_WAIT1(); } else { CP_WAIT0(); }
            __syncthreads();
        }
    }

    const int g  = lane >> 2;
    const int tq = lane & 3;
#pragma unroll
    for (int mt = 0; mt < 2; ++mt) {
        const size_t m0 = bm + wm * 32 + mt * 16 + g;
        const int b0 = (int)(m0 >> 14);
        const int l0 = (int)(m0 & 16383);
        const int b1 = (int)((m0 + 8) >> 14);
        const int l1 = (int)((m0 + 8) & 16383);
#pragma unroll
        for (int nt = 0; nt < 6; ++nt) {
            const int n = wn * 48 + nt * 8 + 2 * tq;
            OUT[((size_t)b0 * DMODEL + n)     * LIMG + l0] = acc[mt][nt][0];
            OUT[((size_t)b0 * DMODEL + n + 1) * LIMG + l0] = acc[mt][nt][1];
            OUT[((size_t)b1 * DMODEL + n)     * LIMG + l1] = acc[mt][nt][2];
            OUT[((size_t)b1 * DMODEL + n + 1) * LIMG + l1] = acc[mt][nt][3];
        }
    }
#undef G3_CP
}

// =====================================================================
extern "C" void kernel_launch(void* const* d_in, const int* in_sizes, int n_in,
                              void* d_out, int out_size) {
    (void)in_sizes; (void)n_in; (void)out_size;
    const float* x      = (const float*)d_in[0];
    const float* w_in   = (const float*)d_in[1];
    const float* w_conv = (const float*)d_in[2];
    const float* b_conv = (const float*)d_in[3];
    const float* w_x    = (const float*)d_in[4];
    const float* w_dt   = (const float*)d_in[5];
    const float* b_dt   = (const float*)d_in[6];
    const float* D_skip = (const float*)d_in[7];
    const float* w_out  = (const float*)d_in[8];
    const float* gamma  = (const float*)d_in[9];
    const float* beta   = (const float*)d_in[10];
    float* out = (float*)d_out;

    const int g1_smem   = 3 * G1_HBUF * 2;                          // 60 KB
    const int g3_smem   = 3 * G3_HBUF * 2;                          // 48 KB
    const int conv_smem = 324 * 64 * 2 + (9 * 64 + 64) * 4;         // ~44 KB
    const int xs_smem   = (2 * DINNER * XS_BSTRIDE + 2 * XS_ABUF) * 2; // ~94 KB
    cudaFuncSetAttribute(gemm_proj_f16,
        cudaFuncAttributeMaxDynamicSharedMemorySize, g1_smem);
    cudaFuncSetAttribute(gemm_out_f16,
        cudaFuncAttributeMaxDynamicSharedMemorySize, g3_smem);
    cudaFuncSetAttribute(conv_kernel,
        cudaFuncAttributeMaxDynamicSharedMemorySize, conv_smem);
    cudaFuncSetAttribute(xssm_mma_kernel,
        cudaFuncAttributeMaxDynamicSharedMemorySize, xs_smem);

    // 0. fp32 -> fp16 weight conversions
    convert_kernel<<<256, 256>>>(w_in, w_out, w_x);

    // 1. projection GEMM (3-stage cp.async)
    dim3 g1(NPROJ / 256, MROWS / 64);
    gemm_proj_f16<<<g1, 256, g1_smem>>>(x);

    // 2. depthwise conv + silu
    dim3 g2(6, 8, 64);
    conv_kernel<<<g2, 256, conv_smem>>>(w_conv, b_conv);

    // 3. XSSM via fp16 MMA (2-stage cp.async)
    xssm_mma_kernel<<<MROWS / 128, 256, xs_smem>>>();

    // 4. pointwise dt/gate/LN
    point_kernel<<<MROWS / 64, 256>>>(w_dt, b_dt, D_skip, gamma, beta);

    // 5. output GEMM (3-stage cp.async, transposed scatter write)
    gemm_out_f16<<<MROWS / 64, 256, g3_smem>>>(out);
}